// round 13
// baseline (speedup 1.0000x reference)
#include <cuda_runtime.h>
#include <cuda_fp16.h>
#include <math.h>
#include <stdint.h>

#define BB 64
#define TT 2048
#define DD 256
#define EPSV 1e-7f

// Scratch (device globals — no allocations allowed)
__device__ float g_denom[BB];         // sum over T (EPS added in norm)

// Pre-converted W (fp16) in MMA B-fragment order:
// [slab(8)][warp(8)][q(4)][lane(32)] uint4; u = q*4+c in 0..15:
// kk=u>>3, j=(u>>1)&3, r=u&1; e = warp*32 + j*8 + gid; p = slab*16 + kk*8 + tig + 4r
// value = pack_h(W[2p][e], W[2p+1][e])
// => for e-half h (j in {2h,2h+1}): q = 2*kk + h, words (2j',2j'+1), j'=j-2h.
__device__ uint4 g_wfrag[8][8][4][32];   // 128 KB

// smem row stride for the x tile, in 32-bit words. 132 words = 528 B = 33*16:
// every ldmatrix row address stays 16B-aligned, and 528 mod 128 = 16 so the
// 8 rows of each 8x8 matrix land on distinct 128B phases -> conflict-free LDSM.
#define XSTR 132

// ---------------- helpers ----------------
__device__ __forceinline__ uint32_t smem_u32(const void* p) {
    uint32_t a;
    asm("{ .reg .u64 t; cvta.to.shared.u64 t, %1; cvt.u32.u64 %0, t; }"
        : "=r"(a) : "l"(p));
    return a;
}
__device__ __forceinline__ unsigned pack_h(float a, float b) {
    __half2 h = __floats2half2_rn(a, b);
    return *reinterpret_cast<unsigned*>(&h);
}
__device__ __forceinline__ float tanh_fast(float v) {
    float y; asm("tanh.approx.f32 %0, %1;" : "=f"(y) : "f"(v)); return y;
}
__device__ __forceinline__ void mma_f16(float c[4], const unsigned a[4],
                                        const unsigned b0, const unsigned b1) {
    asm volatile(
        "mma.sync.aligned.m16n8k16.row.col.f32.f16.f16.f32 "
        "{%0,%1,%2,%3}, {%4,%5,%6,%7}, {%8,%9}, {%0,%1,%2,%3};\n"
        : "+f"(c[0]), "+f"(c[1]), "+f"(c[2]), "+f"(c[3])
        : "r"(a[0]), "r"(a[1]), "r"(a[2]), "r"(a[3]), "r"(b0), "r"(b1));
}
__device__ __forceinline__ void ldsm_x4(unsigned r[4], uint32_t addr) {
    asm volatile("ldmatrix.sync.aligned.m8n8.x4.shared.b16 {%0,%1,%2,%3}, [%4];"
                 : "=r"(r[0]), "=r"(r[1]), "=r"(r[2]), "=r"(r[3]) : "r"(addr));
}

// ---------------------------------------------------------------------------
// K0: one-shot convert of W to fp16 B-fragments; also zeroes out + g_denom.
// One 32-bit output word per thread: 32768 threads (128 blocks), 2 LDGs each,
// fully coalesced stores. Linear index t maps to [slab][wrp][q][lane].word.
// ---------------------------------------------------------------------------
__global__ __launch_bounds__(256) void wsplit_kernel(const float* __restrict__ W,
                                                     float* __restrict__ out)
{
    const int t = blockIdx.x * 256 + threadIdx.x;      // 0..32767
    if (t < BB) g_denom[t] = 0.0f;
    if (t < BB * DD) out[t] = 0.0f;

    const int word = t & 3;
    const int lane = (t >> 2) & 31;
    const int q    = (t >> 7) & 3;
    const int wrp  = (t >> 9) & 7;
    const int slab = t >> 12;
    const int gid  = lane >> 2;
    const int tig  = lane & 3;

    const int u  = q * 4 + word;
    const int kk = u >> 3;
    const int j  = (u >> 1) & 3;
    const int r  = u & 1;
    const int e  = wrp * 32 + j * 8 + gid;
    const int p  = slab * 16 + kk * 8 + tig + 4 * r;

    reinterpret_cast<unsigned*>(&g_wfrag[0][0][0][0])[(size_t)t] =
        pack_h(W[(size_t)(2 * p) * DD + e], W[(size_t)(2 * p + 1) * DD + e]);
}

// ---------------------------------------------------------------------------
// K1: fused  a = exp( uw . tanh(x @ W + b) ) * mask   AND the weighted sum.
// Single fp16 MMA pass; per-warp N=32 processed in two e-halves of 16 so the
// live accumulator set is 32 regs -> 3 CTAs/SM.
// ---------------------------------------------------------------------------
__global__ __launch_bounds__(256, 3) void score_kernel(
    const float* __restrict__ x,
    const float* __restrict__ bias, const float* __restrict__ uw,
    const int* __restrict__ mask, float* __restrict__ out)
{
    __shared__ __align__(16) unsigned xs[64][XSTR];   // fp16 pairs, 33.8 KB
    __shared__ float sbias[256], suw[256];
    __shared__ float red[64][9];
    __shared__ float sa[64];

    const int tid  = threadIdx.x;
    const int warp = tid >> 5;
    const int lane = tid & 31;
    const int gid  = lane >> 2;
    const int tig  = lane & 3;
    const long tile0 = (long)blockIdx.x * 64;
    const int  batch = blockIdx.x >> 5;    // 32 blocks per batch

    sbias[tid] = bias[tid];
    suw[tid]   = uw[tid];

    // ldmatrix per-lane address offset
    const int lrow = lane & 15;
    const int lcol = (lane & 16) >> 2;          // +4 words for mats 2/3
    const uint32_t xs_base = smem_u32(&xs[0][0]);
    const uint32_t lofs = (uint32_t)(lrow * XSTR + lcol) * 4u;

    // ---- stage the full 64x256 x tile as fp16 pairs; uint4 STS (8 iters) ----
    #pragma unroll
    for (int q = 0; q < 8; q++) {
        const int idx = q * 256 + tid;          // 0..2047 chunks of 32B
        const int row = idx >> 5;
        const int c8  = idx & 31;               // 8-float chunk within row
        const float4 va = *reinterpret_cast<const float4*>(
            &x[(tile0 + row) * DD + c8 * 8]);
        const float4 vb = *reinterpret_cast<const float4*>(
            &x[(tile0 + row) * DD + c8 * 8 + 4]);
        uint4 pck;
        pck.x = pack_h(va.x, va.y);
        pck.y = pack_h(va.z, va.w);
        pck.z = pack_h(vb.x, vb.y);
        pck.w = pack_h(vb.z, vb.w);
        *reinterpret_cast<uint4*>(&xs[row][c8 * 4]) = pck;
    }
    __syncthreads();

    const int n0 = warp * 32;
    float tsum[4][2];
    #pragma unroll
    for (int i = 0; i < 4; i++) { tsum[i][0] = 0.0f; tsum[i][1] = 0.0f; }

    // ---- two e-halves of 16 columns each; acc reused across halves ----
    #pragma unroll 1
    for (int h = 0; h < 2; h++) {
        float acc[4][2][4];
        #pragma unroll
        for (int i = 0; i < 4; i++)
            #pragma unroll
            for (int j = 0; j < 2; j++)
                #pragma unroll
                for (int q = 0; q < 4; q++) acc[i][j][q] = 0.0f;

        #pragma unroll
        for (int s = 0; s < 8; s++) {
            const uint4* bp = &g_wfrag[s][warp][0][lane];
            const uint4 q0 = bp[h * 32];            // kk = 0, this half
            const uint4 q1 = bp[(2 + h) * 32];      // kk = 1, this half
            #pragma unroll
            for (int kk = 0; kk < 2; kk++) {
                const uint4 qq = kk ? q1 : q0;
                #pragma unroll
                for (int i = 0; i < 4; i++) {
                    const uint32_t fo =
                        (uint32_t)(i * 16 * XSTR + s * 16 + kk * 8) * 4u + lofs;
                    unsigned ah[4];
                    ldsm_x4(ah, xs_base + fo);
                    mma_f16(acc[i][0], ah, qq.x, qq.y);
                    mma_f16(acc[i][1], ah, qq.z, qq.w);
                }
            }
        }

        // partial epilogue for this half: accumulate tanh(v+b)*uw into tsum
        #pragma unroll
        for (int i = 0; i < 4; i++) {
            #pragma unroll
            for (int j = 0; j < 2; j++) {
                const int e = n0 + (2 * h + j) * 8 + tig * 2;
                const float b0 = sbias[e], b1 = sbias[e + 1];
                const float u0 = suw[e],   u1 = suw[e + 1];
                tsum[i][0] += tanh_fast(acc[i][j][0] + b0) * u0
                            + tanh_fast(acc[i][j][1] + b1) * u1;
                tsum[i][1] += tanh_fast(acc[i][j][2] + b0) * u0
                            + tanh_fast(acc[i][j][3] + b1) * u1;
            }
        }
    }

    // ---- cross-thread reduce of the row scores ----
    #pragma unroll
    for (int i = 0; i < 4; i++) {
        float s0 = tsum[i][0], s1 = tsum[i][1];
        s0 += __shfl_xor_sync(0xffffffffu, s0, 1);
        s0 += __shfl_xor_sync(0xffffffffu, s0, 2);
        s1 += __shfl_xor_sync(0xffffffffu, s1, 1);
        s1 += __shfl_xor_sync(0xffffffffu, s1, 2);
        if (tig == 0) {
            red[i * 16 + gid    ][warp] = s0;
            red[i * 16 + gid + 8][warp] = s1;
        }
    }
    __syncthreads();

    if (tid < 64) {
        float s = 0.0f;
        #pragma unroll
        for (int w = 0; w < 8; w++) s += red[tid][w];
        const long gi = tile0 + tid;
        const float a = __expf(s) * (float)mask[gi];
        sa[tid] = a;
        float ws = a;
        #pragma unroll
        for (int off = 16; off; off >>= 1)
            ws += __shfl_xor_sync(0xffffffffu, ws, off);
        if (lane == 0) atomicAdd(&g_denom[batch], ws);
    }
    __syncthreads();

    // ---- fused weighted sum: out[b, dq..dq+3] += sum_t a_t * x[t, dq..dq+3]
    // thread covers one d-quad for 16 of the 64 tokens; x tile is L2-hot.
    {
        const int dq = (tid & 63) * 4;
        const int tg = tid >> 6;               // t-group 0..3
        const float* xp = &x[(tile0 + tg * 16) * DD + dq];
        float4 a4 = make_float4(0.f, 0.f, 0.f, 0.f);
        #pragma unroll
        for (int t = 0; t < 16; t++) {
            const float4 v = *reinterpret_cast<const float4*>(xp + (size_t)t * DD);
            const float w = sa[tg * 16 + t];
            a4.x = fmaf(v.x, w, a4.x);
            a4.y = fmaf(v.y, w, a4.y);
            a4.z = fmaf(v.z, w, a4.z);
            a4.w = fmaf(v.w, w, a4.w);
        }
        float* op = &out[batch * DD + dq];
        atomicAdd(op + 0, a4.x);
        atomicAdd(op + 1, a4.y);
        atomicAdd(op + 2, a4.z);
        atomicAdd(op + 3, a4.w);
    }
}

// ---------------------------------------------------------------------------
// K2: out[b,d] /= (denom[b] + EPS)
// ---------------------------------------------------------------------------
__global__ __launch_bounds__(256) void norm_kernel(float* __restrict__ out)
{
    const int b = blockIdx.x;
    out[b * DD + threadIdx.x] *= 1.0f / (g_denom[b] + EPSV);
}

// ---------------------------------------------------------------------------
extern "C" void kernel_launch(void* const* d_in, const int* in_sizes, int n_in,
                              void* d_out, int out_size)
{
    const float* x    = (const float*)d_in[0];
    const float* W    = (const float*)d_in[1];
    const float* bias = (const float*)d_in[2];
    const float* uw   = (const float*)d_in[3];
    const int*   mask = (const int*)d_in[4];
    float* out = (float*)d_out;

    wsplit_kernel<<<128, 256>>>(W, out);
    score_kernel<<<(BB * TT) / 64, 256>>>(x, bias, uw, mask, out);
    norm_kernel<<<BB, 256>>>(out);
}

// round 15
// speedup vs baseline: 1.1213x; 1.1213x over previous
#include <cuda_runtime.h>
#include <cuda_fp16.h>
#include <math.h>
#include <stdint.h>

#define BB 64
#define TT 2048
#define DD 256
#define EPSV 1e-7f

// Scratch (device globals — no allocations allowed)
__device__ float g_denom[BB];         // sum over T (EPS added in norm)

// Pre-converted W (fp16) in MMA B-fragment order:
// [slab(8)][warp(8)][q(4)][lane(32)] uint4; u = q*4+c in 0..15:
// kk=u>>3, j=(u>>1)&3, r=u&1; e = warp*32 + j*8 + gid; p = slab*16 + kk*8 + tig + 4r
// value = pack_h(W[2p][e], W[2p+1][e])
__device__ uint4 g_wfrag[8][8][4][32];   // 128 KB

// smem row stride for the x tile, in 32-bit words. 132 words = 528 B = 33*16:
// every ldmatrix row address stays 16B-aligned, and 528 mod 128 = 16 so the
// 8 rows of each 8x8 matrix land on distinct 128B phases -> conflict-free LDSM.
#define XSTR 132

// ---------------- helpers ----------------
__device__ __forceinline__ uint32_t smem_u32(const void* p) {
    uint32_t a;
    asm("{ .reg .u64 t; cvta.to.shared.u64 t, %1; cvt.u32.u64 %0, t; }"
        : "=r"(a) : "l"(p));
    return a;
}
__device__ __forceinline__ unsigned pack_h(float a, float b) {
    __half2 h = __floats2half2_rn(a, b);
    return *reinterpret_cast<unsigned*>(&h);
}
__device__ __forceinline__ float tanh_fast(float v) {
    float y; asm("tanh.approx.f32 %0, %1;" : "=f"(y) : "f"(v)); return y;
}
__device__ __forceinline__ void mma_f16(float c[4], const unsigned a[4],
                                        const unsigned b0, const unsigned b1) {
    asm volatile(
        "mma.sync.aligned.m16n8k16.row.col.f32.f16.f16.f32 "
        "{%0,%1,%2,%3}, {%4,%5,%6,%7}, {%8,%9}, {%0,%1,%2,%3};\n"
        : "+f"(c[0]), "+f"(c[1]), "+f"(c[2]), "+f"(c[3])
        : "r"(a[0]), "r"(a[1]), "r"(a[2]), "r"(a[3]), "r"(b0), "r"(b1));
}
__device__ __forceinline__ void ldsm_x4(unsigned r[4], uint32_t addr) {
    asm volatile("ldmatrix.sync.aligned.m8n8.x4.shared.b16 {%0,%1,%2,%3}, [%4];"
                 : "=r"(r[0]), "=r"(r[1]), "=r"(r[2]), "=r"(r[3]) : "r"(addr));
}

// ---------------------------------------------------------------------------
// K0: one-shot convert of W to fp16 B-fragments; also zeroes out + g_denom.
// One 32-bit output word per thread: 32768 threads (128 blocks), 2 LDGs each,
// fully coalesced stores. Linear index t maps to [slab][wrp][q][lane].word.
// ---------------------------------------------------------------------------
__global__ __launch_bounds__(256) void wsplit_kernel(const float* __restrict__ W,
                                                     float* __restrict__ out)
{
    const int t = blockIdx.x * 256 + threadIdx.x;      // 0..32767
    if (t < BB) g_denom[t] = 0.0f;
    if (t < BB * DD) out[t] = 0.0f;

    const int word = t & 3;
    const int lane = (t >> 2) & 31;
    const int q    = (t >> 7) & 3;
    const int wrp  = (t >> 9) & 7;
    const int slab = t >> 12;
    const int gid  = lane >> 2;
    const int tig  = lane & 3;

    const int u  = q * 4 + word;
    const int kk = u >> 3;
    const int j  = (u >> 1) & 3;
    const int r  = u & 1;
    const int e  = wrp * 32 + j * 8 + gid;
    const int p  = slab * 16 + kk * 8 + tig + 4 * r;

    reinterpret_cast<unsigned*>(&g_wfrag[0][0][0][0])[(size_t)t] =
        pack_h(W[(size_t)(2 * p) * DD + e], W[(size_t)(2 * p + 1) * DD + e]);
}

// ---------------------------------------------------------------------------
// K1: fused  a = exp( uw . tanh(x @ W + b) ) * mask   AND the weighted sum:
// atomically accumulates  out[b,d] += sum_t a_t * x[t,d]   (numerator, x from
// the smem fp16 tile) and g_denom[b] += sum_t a_t.  Single fp16 MMA pass.
// Block: 256 thr (8 warps). Tile M=64 tokens x N=256, full K=256 in smem.
// ---------------------------------------------------------------------------
__global__ __launch_bounds__(256, 2) void score_kernel(
    const float* __restrict__ x,
    const float* __restrict__ bias, const float* __restrict__ uw,
    const int* __restrict__ mask, float* __restrict__ out)
{
    __shared__ __align__(16) unsigned xs[64][XSTR];   // fp16 pairs, 33.8 KB
    __shared__ float sbias[256], suw[256];
    __shared__ float red[64][9];
    __shared__ float sa[64];

    const int tid  = threadIdx.x;
    const int warp = tid >> 5;
    const int lane = tid & 31;
    const int gid  = lane >> 2;
    const int tig  = lane & 3;
    const long tile0 = (long)blockIdx.x * 64;
    const int  batch = blockIdx.x >> 5;    // 32 blocks per batch

    sbias[tid] = bias[tid];
    suw[tid]   = uw[tid];

    // ldmatrix per-lane address offset
    const int lrow = lane & 15;
    const int lcol = (lane & 16) >> 2;          // +4 words for mats 2/3
    const uint32_t xs_base = smem_u32(&xs[0][0]);
    const uint32_t lofs = (uint32_t)(lrow * XSTR + lcol) * 4u;

    // ---- stage the full 64x256 x tile as fp16 pairs; uint4 STS (8 iters) ----
    #pragma unroll
    for (int q = 0; q < 8; q++) {
        const int idx = q * 256 + tid;          // 0..2047 chunks of 32B
        const int row = idx >> 5;
        const int c8  = idx & 31;               // 8-float chunk within row
        const float4 va = *reinterpret_cast<const float4*>(
            &x[(tile0 + row) * DD + c8 * 8]);
        const float4 vb = *reinterpret_cast<const float4*>(
            &x[(tile0 + row) * DD + c8 * 8 + 4]);
        uint4 pck;
        pck.x = pack_h(va.x, va.y);
        pck.y = pack_h(va.z, va.w);
        pck.z = pack_h(vb.x, vb.y);
        pck.w = pack_h(vb.z, vb.w);
        *reinterpret_cast<uint4*>(&xs[row][c8 * 4]) = pck;
    }
    __syncthreads();

    float acc[4][4][4];
    #pragma unroll
    for (int i = 0; i < 4; i++)
        #pragma unroll
        for (int j = 0; j < 4; j++)
            #pragma unroll
            for (int q = 0; q < 4; q++) acc[i][j][q] = 0.0f;

    // ---- MMA: 8 slabs x 2 kk x 4 i x 4 j = 256 HMMA per warp ----
    #pragma unroll
    for (int s = 0; s < 8; s++) {
        const uint4* bp = &g_wfrag[s][warp][0][lane];
        const uint4 bq0 = bp[0];
        const uint4 bq1 = bp[32];
        const uint4 bq2 = bp[64];
        const uint4 bq3 = bp[96];
        #pragma unroll
        for (int kk = 0; kk < 2; kk++) {
            const uint4 qa = kk ? bq2 : bq0;
            const uint4 qb = kk ? bq3 : bq1;
            const unsigned b[8] = {qa.x, qa.y, qa.z, qa.w, qb.x, qb.y, qb.z, qb.w};
            #pragma unroll
            for (int i = 0; i < 4; i++) {
                const uint32_t fo = (uint32_t)(i * 16 * XSTR + s * 16 + kk * 8) * 4u + lofs;
                unsigned ah[4];
                ldsm_x4(ah, xs_base + fo);
                #pragma unroll
                for (int j = 0; j < 4; j++)
                    mma_f16(acc[i][j], ah, b[j * 2], b[j * 2 + 1]);
            }
        }
    }

    // ---- epilogue: per-row  sum_e tanh(v + b[e]) * uw[e] ----
    const int n0 = warp * 32;
    #pragma unroll
    for (int i = 0; i < 4; i++) {
        float s0 = 0.0f, s1 = 0.0f;
        #pragma unroll
        for (int j = 0; j < 4; j++) {
            const int e = n0 + j * 8 + tig * 2;
            const float b0 = sbias[e], b1 = sbias[e + 1];
            const float u0 = suw[e],   u1 = suw[e + 1];
            s0 += tanh_fast(acc[i][j][0] + b0) * u0 + tanh_fast(acc[i][j][1] + b1) * u1;
            s1 += tanh_fast(acc[i][j][2] + b0) * u0 + tanh_fast(acc[i][j][3] + b1) * u1;
        }
        s0 += __shfl_xor_sync(0xffffffffu, s0, 1);
        s0 += __shfl_xor_sync(0xffffffffu, s0, 2);
        s1 += __shfl_xor_sync(0xffffffffu, s1, 1);
        s1 += __shfl_xor_sync(0xffffffffu, s1, 2);
        if (tig == 0) {
            red[i * 16 + gid    ][warp] = s0;
            red[i * 16 + gid + 8][warp] = s1;
        }
    }
    __syncthreads();

    if (tid < 64) {
        float s = 0.0f;
        #pragma unroll
        for (int w = 0; w < 8; w++) s += red[tid][w];
        const long gi = tile0 + tid;
        const float a = __expf(s) * (float)mask[gi];
        sa[tid] = a;
        float ws = a;
        #pragma unroll
        for (int off = 16; off; off >>= 1)
            ws += __shfl_xor_sync(0xffffffffu, ws, off);
        if (lane == 0) atomicAdd(&g_denom[batch], ws);
    }
    __syncthreads();

    // ---- fused weighted sum from the SMEM fp16 tile (no global re-read):
    // out[b, dq..dq+3] += sum_t a_t * x[t, dq..dq+3]
    // thread covers one d-quad for 16 of the 64 tokens.
    {
        const int dq = (tid & 63) * 4;
        const int tg = tid >> 6;               // t-group 0..3
        float4 a4 = make_float4(0.f, 0.f, 0.f, 0.f);
        #pragma unroll
        for (int t = 0; t < 16; t++) {
            const int row = tg * 16 + t;
            const uint2 pk = *reinterpret_cast<const uint2*>(&xs[row][dq >> 1]);
            const float2 v01 = __half22float2(*reinterpret_cast<const __half2*>(&pk.x));
            const float2 v23 = __half22float2(*reinterpret_cast<const __half2*>(&pk.y));
            const float w = sa[row];
            a4.x = fmaf(v01.x, w, a4.x);
            a4.y = fmaf(v01.y, w, a4.y);
            a4.z = fmaf(v23.x, w, a4.z);
            a4.w = fmaf(v23.y, w, a4.w);
        }
        float* op = &out[batch * DD + dq];
        atomicAdd(op + 0, a4.x);
        atomicAdd(op + 1, a4.y);
        atomicAdd(op + 2, a4.z);
        atomicAdd(op + 3, a4.w);
    }
}

// ---------------------------------------------------------------------------
// K2: out[b,d] /= (denom[b] + EPS)
// ---------------------------------------------------------------------------
__global__ __launch_bounds__(256) void norm_kernel(float* __restrict__ out)
{
    const int b = blockIdx.x;
    out[b * DD + threadIdx.x] *= 1.0f / (g_denom[b] + EPSV);
}

// ---------------------------------------------------------------------------
extern "C" void kernel_launch(void* const* d_in, const int* in_sizes, int n_in,
                              void* d_out, int out_size)
{
    const float* x    = (const float*)d_in[0];
    const float* W    = (const float*)d_in[1];
    const float* bias = (const float*)d_in[2];
    const float* uw   = (const float*)d_in[3];
    const int*   mask = (const int*)d_in[4];
    float* out = (float*)d_out;

    wsplit_kernel<<<128, 256>>>(W, out);
    score_kernel<<<(BB * TT) / 64, 256>>>(x, bias, uw, mask, out);
    norm_kernel<<<BB, 256>>>(out);
}

// round 16
// speedup vs baseline: 1.1446x; 1.0208x over previous
#include <cuda_runtime.h>
#include <cuda_fp16.h>
#include <math.h>
#include <stdint.h>

#define BB 64
#define TT 2048
#define DD 256
#define EPSV 1e-7f

// Scratch (device globals — no allocations allowed)
__device__ float g_denom[BB];         // sum over T (EPS added in norm)

// Pre-converted W (fp16) in MMA B-fragment order:
// [slab(8)][warp(8)][q(4)][lane(32)] uint4; u = q*4+word in 0..15:
// kk=u>>3, j=(u>>1)&3, r=u&1; e = warp*32 + j*8 + gid; p = slab*16 + kk*8 + tig + 4r
// value = pack_h(W[2p][e], W[2p+1][e])
__device__ uint4 g_wfrag[8][8][4][32];   // 128 KB

// smem row stride for the x tile, in 32-bit words. 132 words = 528 B = 33*16:
// every ldmatrix row address stays 16B-aligned, and 528 mod 128 = 16 so the
// 8 rows of each 8x8 matrix land on distinct 128B phases -> conflict-free LDSM.
#define XSTR 132

// ---------------- helpers ----------------
__device__ __forceinline__ uint32_t smem_u32(const void* p) {
    uint32_t a;
    asm("{ .reg .u64 t; cvta.to.shared.u64 t, %1; cvt.u32.u64 %0, t; }"
        : "=r"(a) : "l"(p));
    return a;
}
__device__ __forceinline__ unsigned pack_h(float a, float b) {
    __half2 h = __floats2half2_rn(a, b);
    return *reinterpret_cast<unsigned*>(&h);
}
__device__ __forceinline__ float tanh_fast(float v) {
    float y; asm("tanh.approx.f32 %0, %1;" : "=f"(y) : "f"(v)); return y;
}
__device__ __forceinline__ void mma_f16(float c[4], const unsigned a[4],
                                        const unsigned b0, const unsigned b1) {
    asm volatile(
        "mma.sync.aligned.m16n8k16.row.col.f32.f16.f16.f32 "
        "{%0,%1,%2,%3}, {%4,%5,%6,%7}, {%8,%9}, {%0,%1,%2,%3};\n"
        : "+f"(c[0]), "+f"(c[1]), "+f"(c[2]), "+f"(c[3])
        : "r"(a[0]), "r"(a[1]), "r"(a[2]), "r"(a[3]), "r"(b0), "r"(b1));
}
__device__ __forceinline__ void ldsm_x4(unsigned r[4], uint32_t addr) {
    asm volatile("ldmatrix.sync.aligned.m8n8.x4.shared.b16 {%0,%1,%2,%3}, [%4];"
                 : "=r"(r[0]), "=r"(r[1]), "=r"(r[2]), "=r"(r[3]) : "r"(addr));
}

// ---------------------------------------------------------------------------
// K0: one-shot convert of W to fp16 B-fragments; also zeroes out + g_denom.
// Thread = (p, e-quad): two COALESCED LDG.128 of W rows 2p / 2p+1, then four
// scattered 4B stores into fragment order (stores don't stall).
// 8192 threads (32 blocks).
// ---------------------------------------------------------------------------
__global__ __launch_bounds__(256) void wsplit_kernel(const float* __restrict__ W,
                                                     float* __restrict__ out)
{
    const int gidx = blockIdx.x * 256 + threadIdx.x;   // 0..8191
    if (gidx < BB) g_denom[gidx] = 0.0f;
    out[gidx] = 0.0f;
    out[gidx + 8192] = 0.0f;

    const int p  = gidx >> 6;          // 0..127 (k-pair index)
    const int et = gidx & 63;          // e-quad index; e = 4*et
    const int e0 = et * 4;

    const float4 va = *reinterpret_cast<const float4*>(&W[(size_t)(2 * p) * DD + e0]);
    const float4 vb = *reinterpret_cast<const float4*>(&W[(size_t)(2 * p + 1) * DD + e0]);
    const float a[4] = {va.x, va.y, va.z, va.w};
    const float b[4] = {vb.x, vb.y, vb.z, vb.w};

    // decode p: p = slab*16 + kk*8 + 4r + tig
    const int slab = p >> 4;
    const int kk   = (p >> 3) & 1;
    const int r    = (p >> 2) & 1;
    const int tig  = p & 3;

    unsigned* wf = reinterpret_cast<unsigned*>(&g_wfrag[0][0][0][0]);
    #pragma unroll
    for (int c = 0; c < 4; c++) {
        const int e    = e0 + c;
        const int wrp  = e >> 5;
        const int j    = (e >> 3) & 3;
        const int gid  = e & 7;
        const int lane = gid * 4 + tig;
        const int u    = kk * 8 + j * 2 + r;
        const int q    = u >> 2;
        const int word = u & 3;
        wf[(((size_t)(slab * 8 + wrp) * 4 + q) * 32 + lane) * 4 + word] =
            pack_h(a[c], b[c]);
    }
}

// ---------------------------------------------------------------------------
// K1: fused  a = exp( uw . tanh(x @ W + b) ) * mask   AND the weighted sum:
// out[b,d] += sum_t a_t * x[t,d] (numerator, x from the smem fp16 tile) and
// g_denom[b] += sum_t a_t.  Single fp16 MMA pass; B fragments software-
// pipelined one slab ahead so their L2 latency hides under the MMAs.
// Block: 256 thr (8 warps). Tile M=64 tokens x N=256, full K=256 in smem.
// ---------------------------------------------------------------------------
__global__ __launch_bounds__(256, 2) void score_kernel(
    const float* __restrict__ x,
    const float* __restrict__ bias, const float* __restrict__ uw,
    const int* __restrict__ mask, float* __restrict__ out)
{
    __shared__ __align__(16) unsigned xs[64][XSTR];   // fp16 pairs, 33.8 KB
    __shared__ float sbias[256], suw[256];
    __shared__ float red[64][9];
    __shared__ float sa[64];

    const int tid  = threadIdx.x;
    const int warp = tid >> 5;
    const int lane = tid & 31;
    const int gid  = lane >> 2;
    const int tig  = lane & 3;
    const long tile0 = (long)blockIdx.x * 64;
    const int  batch = blockIdx.x >> 5;    // 32 blocks per batch

    sbias[tid] = bias[tid];
    suw[tid]   = uw[tid];

    // ldmatrix per-lane address offset
    const int lrow = lane & 15;
    const int lcol = (lane & 16) >> 2;          // +4 words for mats 2/3
    const uint32_t xs_base = smem_u32(&xs[0][0]);
    const uint32_t lofs = (uint32_t)(lrow * XSTR + lcol) * 4u;

    // ---- stage the full 64x256 x tile as fp16 pairs; uint4 STS (8 iters) ----
    #pragma unroll
    for (int q = 0; q < 8; q++) {
        const int idx = q * 256 + tid;          // 0..2047 chunks of 32B
        const int row = idx >> 5;
        const int c8  = idx & 31;               // 8-float chunk within row
        const float4 va = *reinterpret_cast<const float4*>(
            &x[(tile0 + row) * DD + c8 * 8]);
        const float4 vb = *reinterpret_cast<const float4*>(
            &x[(tile0 + row) * DD + c8 * 8 + 4]);
        uint4 pck;
        pck.x = pack_h(va.x, va.y);
        pck.y = pack_h(va.z, va.w);
        pck.z = pack_h(vb.x, vb.y);
        pck.w = pack_h(vb.z, vb.w);
        *reinterpret_cast<uint4*>(&xs[row][c8 * 4]) = pck;
    }

    float acc[4][4][4];
    #pragma unroll
    for (int i = 0; i < 4; i++)
        #pragma unroll
        for (int j = 0; j < 4; j++)
            #pragma unroll
            for (int q = 0; q < 4; q++) acc[i][j][q] = 0.0f;

    // prefetch slab 0's B fragments (overlaps the staging barrier)
    const uint4* bp0 = &g_wfrag[0][warp][0][lane];
    uint4 nb0 = bp0[0];
    uint4 nb1 = bp0[32];
    uint4 nb2 = bp0[64];
    uint4 nb3 = bp0[96];

    __syncthreads();

    // ---- MMA: 8 slabs x 2 kk x 4 i x 4 j = 256 HMMA per warp,
    //      B fragments pipelined one slab ahead ----
    #pragma unroll
    for (int s = 0; s < 8; s++) {
        const uint4 bq0 = nb0, bq1 = nb1, bq2 = nb2, bq3 = nb3;
        if (s < 7) {
            const uint4* bp = &g_wfrag[s + 1][warp][0][lane];
            nb0 = bp[0]; nb1 = bp[32]; nb2 = bp[64]; nb3 = bp[96];
        }
        #pragma unroll
        for (int kk = 0; kk < 2; kk++) {
            const uint4 qa = kk ? bq2 : bq0;
            const uint4 qb = kk ? bq3 : bq1;
            const unsigned b[8] = {qa.x, qa.y, qa.z, qa.w, qb.x, qb.y, qb.z, qb.w};
            #pragma unroll
            for (int i = 0; i < 4; i++) {
                const uint32_t fo = (uint32_t)(i * 16 * XSTR + s * 16 + kk * 8) * 4u + lofs;
                unsigned ah[4];
                ldsm_x4(ah, xs_base + fo);
                #pragma unroll
                for (int j = 0; j < 4; j++)
                    mma_f16(acc[i][j], ah, b[j * 2], b[j * 2 + 1]);
            }
        }
    }

    // ---- epilogue: per-row  sum_e tanh(v + b[e]) * uw[e] ----
    const int n0 = warp * 32;
    #pragma unroll
    for (int i = 0; i < 4; i++) {
        float s0 = 0.0f, s1 = 0.0f;
        #pragma unroll
        for (int j = 0; j < 4; j++) {
            const int e = n0 + j * 8 + tig * 2;
            const float b0 = sbias[e], b1 = sbias[e + 1];
            const float u0 = suw[e],   u1 = suw[e + 1];
            s0 += tanh_fast(acc[i][j][0] + b0) * u0 + tanh_fast(acc[i][j][1] + b1) * u1;
            s1 += tanh_fast(acc[i][j][2] + b0) * u0 + tanh_fast(acc[i][j][3] + b1) * u1;
        }
        s0 += __shfl_xor_sync(0xffffffffu, s0, 1);
        s0 += __shfl_xor_sync(0xffffffffu, s0, 2);
        s1 += __shfl_xor_sync(0xffffffffu, s1, 1);
        s1 += __shfl_xor_sync(0xffffffffu, s1, 2);
        if (tig == 0) {
            red[i * 16 + gid    ][warp] = s0;
            red[i * 16 + gid + 8][warp] = s1;
        }
    }
    __syncthreads();

    if (tid < 64) {
        float s = 0.0f;
        #pragma unroll
        for (int w = 0; w < 8; w++) s += red[tid][w];
        const long gi = tile0 + tid;
        const float a = __expf(s) * (float)mask[gi];
        sa[tid] = a;
        float ws = a;
        #pragma unroll
        for (int off = 16; off; off >>= 1)
            ws += __shfl_xor_sync(0xffffffffu, ws, off);
        if (lane == 0) atomicAdd(&g_denom[batch], ws);
    }
    __syncthreads();

    // ---- fused weighted sum from the SMEM fp16 tile (no global re-read):
    // out[b, dq..dq+3] += sum_t a_t * x[t, dq..dq+3]
    {
        const int dq = (tid & 63) * 4;
        const int tg = tid >> 6;               // t-group 0..3
        float4 a4 = make_float4(0.f, 0.f, 0.f, 0.f);
        #pragma unroll
        for (int t = 0; t < 16; t++) {
            const int row = tg * 16 + t;
            const uint2 pk = *reinterpret_cast<const uint2*>(&xs[row][dq >> 1]);
            const float2 v01 = __half22float2(*reinterpret_cast<const __half2*>(&pk.x));
            const float2 v23 = __half22float2(*reinterpret_cast<const __half2*>(&pk.y));
            const float w = sa[row];
            a4.x = fmaf(v01.x, w, a4.x);
            a4.y = fmaf(v01.y, w, a4.y);
            a4.z = fmaf(v23.x, w, a4.z);
            a4.w = fmaf(v23.y, w, a4.w);
        }
        float* op = &out[batch * DD + dq];
        atomicAdd(op + 0, a4.x);
        atomicAdd(op + 1, a4.y);
        atomicAdd(op + 2, a4.z);
        atomicAdd(op + 3, a4.w);
    }
}

// ---------------------------------------------------------------------------
// K2: out[b,d] /= (denom[b] + EPS)
// ---------------------------------------------------------------------------
__global__ __launch_bounds__(256) void norm_kernel(float* __restrict__ out)
{
    const int b = blockIdx.x;
    out[b * DD + threadIdx.x] *= 1.0f / (g_denom[b] + EPSV);
}

// ---------------------------------------------------------------------------
extern "C" void kernel_launch(void* const* d_in, const int* in_sizes, int n_in,
                              void* d_out, int out_size)
{
    const float* x    = (const float*)d_in[0];
    const float* W    = (const float*)d_in[1];
    const float* bias = (const float*)d_in[2];
    const float* uw   = (const float*)d_in[3];
    const int*   mask = (const int*)d_in[4];
    float* out = (float*)d_out;

    wsplit_kernel<<<32, 256>>>(W, out);
    score_kernel<<<(BB * TT) / 64, 256>>>(x, bias, uw, mask, out);
    norm_kernel<<<BB, 256>>>(out);
}